// round 12
// baseline (speedup 1.0000x reference)
#include <cuda_runtime.h>
#include <math.h>

#define BATCH 32
#define TT 4096
#define NH 100
#define NH4 25
#define NM 65
#define LAG 149
#define H_ELEMS (BATCH*TT*NH)
#define N_ELEMS (BATCH*TT*NM)
#define PERIOD4 ((TT*NM)/4)          // 66560
#define K3_BLOCKS ((BATCH*TT)/8)     // 16384 (8 warps/block, warp per row)
#define K4_BLOCKS ((N_ELEMS/4)/256)  // 8320
#define K2_THREADS 256
#define FPT 16                       // frames per thread in k2 (256*16 = 4096)

// ---- scratch ----
__device__ float g_h1[H_ELEMS];    // tension*turb result (52MB)
__device__ float g_nf[TT*NM];      // 1 + 0.6*sin(ripple(m)+phase(t))
__device__ float g_cmean[TT];      // batch-mean centroid per t
__device__ float g_mh1[TT*NH];     // batch-mean of h1
__device__ float g_s[TT];          // 0.4*sin(clock(t))

__device__ __forceinline__ float warp_sum(float v) {
    #pragma unroll
    for (int o = 16; o; o >>= 1) v += __shfl_xor_sync(0xffffffffu, v, o);
    return v;
}
// positive floats compare monotonically as uint bits
__device__ __forceinline__ float warp_max_pos(float v) {
    return __uint_as_float(__reduce_max_sync(0xffffffffu, __float_as_uint(v)));
}

// ---------------- K1: one t per block (256 thr, 8 warps x 4 batches) ----------------
// Builds nf table, writes per-row h1 to g_h1, g_cmean[t], g_mh1[t*NH+k].
__global__ void __launch_bounds__(256) k1_reduce(const float* __restrict__ harm) {
    int t = blockIdx.x;
    int w = threadIdx.x >> 5;
    int lane = threadIdx.x & 31;
    int tid = threadIdx.x;

    __shared__ float sturb[104];     // turb row for this t
    __shared__ float part[8*104];    // per-warp partial sums of h1
    __shared__ float cent[32];       // per-batch centroid

    const double TWO_PI_D = 6.283185307179586;
    const double PH_INC   = TWO_PI_D * 40.0 * 64.0 / 16000.0;
    float phasef = (float)fmod((double)(t+1)*PH_INC, TWO_PI_D);

    if (tid < NH) {
        const float OFF_STEP = (float)(4.71238898038469 / 99.0);  // pi*1.5/99
        sturb[tid] = 1.0f + 0.225f * sinf(phasef + (float)tid * OFF_STEP);
    } else if (tid < NH + NM) {
        int m = tid - NH;
        const float RIP_STEP = 7.853981633974483f;                // pi*2.5
        g_nf[t*NM + m] = 1.0f + 0.6f * sinf((float)m * RIP_STEP + phasef);
    }
    __syncthreads();

    bool act = (lane < NH4);
    float4 tb = make_float4(0.f,0.f,0.f,0.f);
    if (act) tb = ((const float4*)sturb)[lane];

    float4 acc = make_float4(0.f,0.f,0.f,0.f);
    #pragma unroll
    for (int j = 0; j < 4; j++) {
        int b = w*4 + j;
        const float4* row4 = (const float4*)(harm + ((size_t)b*TT + t)*NH);
        float4 v = make_float4(0.f,0.f,0.f,0.f);
        if (act) v = __ldg(row4 + lane);
        float mo = act ? fmaxf(fmaxf(fmaxf(1e-6f, v.x), fmaxf(v.y, v.z)), v.w) : 1e-6f;
        mo = warp_max_pos(mo);
        // max(sharp) = mo^3.4 (monotone power), clamped like the reference
        float ms = fmaxf(exp2f(3.4f * __log2f(mo)), 1e-6f);
        float scale = mo / ms;

        float4 h1 = make_float4(0.f,0.f,0.f,0.f);
        float s0 = 0.f, s1 = 0.f;
        if (act) {
            h1.x = exp2f(3.4f * __log2f(fmaxf(v.x, 1e-6f))) * scale * tb.x;
            h1.y = exp2f(3.4f * __log2f(fmaxf(v.y, 1e-6f))) * scale * tb.y;
            h1.z = exp2f(3.4f * __log2f(fmaxf(v.z, 1e-6f))) * scale * tb.z;
            h1.w = exp2f(3.4f * __log2f(fmaxf(v.w, 1e-6f))) * scale * tb.w;
            float k0 = (float)(lane*4);
            s0 = h1.x + h1.y + h1.z + h1.w;
            s1 = h1.x*k0 + h1.y*(k0+1.f) + h1.z*(k0+2.f) + h1.w*(k0+3.f);
            ((float4*)(g_h1 + ((size_t)b*TT + t)*NH))[lane] = h1;   // persist h1
        }
        s0 = warp_sum(s0); s1 = warp_sum(s1);
        if (lane == 0) cent[b] = s1 / fmaxf(s0, 1e-6f);
        acc.x += h1.x; acc.y += h1.y; acc.z += h1.z; acc.w += h1.w;
    }
    if (act) ((float4*)&part[w*104])[lane] = acc;
    __syncthreads();

    if (tid < NH) {                  // 8-way partial reduce, fixed order
        float s = 0.f;
        #pragma unroll
        for (int p = 0; p < 8; p++) s += part[p*104 + tid];
        g_mh1[t*NH + tid] = s * (1.f/32.f);
    }
    if (w == 0) {                    // batch-mean centroid
        float c = cent[lane];
        c = warp_sum(c);
        if (lane == 0) g_cmean[t] = c * (1.f/32.f);
    }
}

// ---------------- K2: single-block scan, warp-level (3 barriers) ----------------
__global__ void __launch_bounds__(K2_THREADS) k2_scan() {
    const double TWO_PI_D = 6.283185307179586;
    const double RATE_K = 0.725 * TWO_PI_D * (64.0/16000.0);
    int tid = threadIdx.x;
    int lane = tid & 31;
    int w = tid >> 5;                // 8 warps

    __shared__ float scm[TT];        // 16KB
    __shared__ double sM[8], sC[8], sS[8];

    for (int i = tid; i < TT; i += K2_THREADS) scm[i] = g_cmean[i];
    __syncthreads();

    // pass A: compose the 16 local steps fb -> 0.9*fb + d into one affine map
    double C = 0.0;
    #pragma unroll
    for (int j = 0; j < FPT; j++) {
        double d = ((double)scm[tid*FPT + j] - 30.0) / 400.0;
        C = 0.9*C + d;
    }
    double Mm = 0.18530201888518424; // 0.9^16
    double Ma = C;
    // warp inclusive affine scan (compose f_prev then f_cur)
    #pragma unroll
    for (int off = 1; off < 32; off <<= 1) {
        double pm = __shfl_up_sync(0xffffffffu, Mm, off);
        double pc = __shfl_up_sync(0xffffffffu, Ma, off);
        if (lane >= off) { Ma = pc*Mm + Ma; Mm = pm*Mm; }
    }
    if (lane == 31) { sM[w] = Mm; sC[w] = Ma; }
    __syncthreads();
    // cross-warp exclusive affine prefix for this warp
    double pC = 0.0;
    for (int p = 0; p < w; p++) { pC = pC*sM[p] + sC[p]; }
    // inclusive end-of-chunk fb for this thread (applied to fb0 = 0)
    double eInc = Mm*pC + Ma;
    double ePrev = __shfl_up_sync(0xffffffffu, eInc, 1);
    double fb0 = (lane == 0) ? pC : ePrev;   // fb entering this thread's chunk

    // pass B: local rate cumsum total
    double fb = fb0, csum = 0.0;
    #pragma unroll
    for (int j = 0; j < FPT; j++) {
        double d = ((double)scm[tid*FPT + j] - 30.0) / 400.0;
        fb = 0.9*fb + d;
        csum += RATE_K*(1.0 + 0.4*fb);
    }
    double s = csum;
    #pragma unroll
    for (int off = 1; off < 32; off <<= 1) {
        double ps = __shfl_up_sync(0xffffffffu, s, off);
        if (lane >= off) s += ps;
    }
    if (lane == 31) sS[w] = s;
    __syncthreads();
    double pS = 0.0;
    for (int p = 0; p < w; p++) pS += sS[p];
    double sPrev = __shfl_up_sync(0xffffffffu, s, 1);
    double base = pS + ((lane == 0) ? 0.0 : sPrev);   // exclusive global prefix

    // pass C: outputs
    fb = fb0; double run = 0.0;
    #pragma unroll
    for (int j = 0; j < FPT; j++) {
        double d = ((double)scm[tid*FPT + j] - 30.0) / 400.0;
        fb = 0.9*fb + d;
        run += RATE_K*(1.0 + 0.4*fb);
        double clock = base + run;
        g_s[tid*FPT + j] = 0.4f * sinf((float)fmod(clock, TWO_PI_D));
    }
}

// ---------------- K34: fused output kernel (h1 precomputed -> pure FMA stream) ----------------
__global__ void __launch_bounds__(256) k34_out(const float4* __restrict__ noise,
                                               float* __restrict__ out) {
    if (blockIdx.x < K3_BLOCKS) {
        // ---- harmonic path: warp per (b,t) row ----
        int wg = (blockIdx.x * 256 + threadIdx.x) >> 5;   // row = b*TT + t
        int lane = threadIdx.x & 31;
        int t = wg & (TT - 1);
        if (lane < NH4) {
            const float4* h1row = (const float4*)(g_h1 + (size_t)wg * NH);
            float4*       orow4 = (float4*)(out + (size_t)wg * NH);

            float st = g_s[t];
            bool has_mem = (t > 0);
            bool has_rd  = (t >= LAG);
            float sp_lag = has_rd ? g_s[t - LAG] : 0.f;

            float4 h1 = __ldg(h1row + lane);
            float k0 = (float)(lane*4);
            float relx = k0*(2.f/99.f) - 1.f;
            float rely = (k0+1.f)*(2.f/99.f) - 1.f;
            float relz = (k0+2.f)*(2.f/99.f) - 1.f;
            float relw = (k0+3.f)*(2.f/99.f) - 1.f;

            float4 h2;
            h2.x = h1.x * (1.f + st*relx);
            h2.y = h1.y * (1.f + st*rely);
            h2.z = h1.z * (1.f + st*relz);
            h2.w = h1.w * (1.f + st*relw);

            float4 o;
            if (!has_mem) {
                o = h2;
            } else if (has_rd) {
                const float4* mh4 = (const float4*)(g_mh1 + (size_t)(t - LAG)*NH);
                float4 m = mh4[lane];
                o.x = 0.6f*h2.x + 0.4f*(1.f + sp_lag*relx)*m.x;
                o.y = 0.6f*h2.y + 0.4f*(1.f + sp_lag*rely)*m.y;
                o.z = 0.6f*h2.z + 0.4f*(1.f + sp_lag*relz)*m.z;
                o.w = 0.6f*h2.w + 0.4f*(1.f + sp_lag*relw)*m.w;
            } else {
                o.x = 0.6f*h2.x; o.y = 0.6f*h2.y; o.z = 0.6f*h2.z; o.w = 0.6f*h2.w;
            }
            orow4[lane] = o;
        }
    } else {
        // ---- noise path: float4 elementwise ----
        unsigned i4 = (blockIdx.x - K3_BLOCKS) * 256 + threadIdx.x;  // < N_ELEMS/4
        unsigned p = i4 % PERIOD4;
        float4* nout4 = (float4*)(out + H_ELEMS);
        float4 n = __ldg(noise + i4);
        float4 f = ((const float4*)g_nf)[p];
        float4 o;
        o.x = n.x*f.x; o.y = n.y*f.y; o.z = n.z*f.z; o.w = n.w*f.w;
        nout4[i4] = o;
    }
}

extern "C" void kernel_launch(void* const* d_in, const int* in_sizes, int n_in,
                              void* d_out, int out_size) {
    const float* harm  = (const float*)d_in[0];
    const float* noise = (const float*)d_in[1];
    float* out = (float*)d_out;

    k1_reduce<<<TT, 256>>>(harm);
    k2_scan<<<1, K2_THREADS>>>();
    k34_out<<<K3_BLOCKS + K4_BLOCKS, 256>>>((const float4*)noise, out);
}